// round 8
// baseline (speedup 1.0000x reference)
#include <cuda_runtime.h>
#include <math.h>
#include <math_constants.h>

#define BATCH 4
#define DIM 256
#define IMG 32
#define NPOS 1024
#define HEADS 8
#define DHEAD 64
#define INNER 512
#define BH 32
#define SCALE 0.125f

// ---------------- scratch (device globals; no allocations) ----------------
static __device__ float d_xt[BATCH * DIM * NPOS];
static __device__ float d_xattn[BATCH * 2 * NPOS];
static __device__ float d_qm[BH * NPOS * 2];
static __device__ float d_km[BH * NPOS * 2];
static __device__ float d_mmax[BH * NPOS];
static __device__ float d_msum[BH * NPOS];
static __device__ int   d_top4[BH * NPOS * 4];
static __device__ float d_y[3 * BATCH * DIM * NPOS];
static __device__ float d_mean[3 * DIM];
static __device__ float d_var[3 * DIM];
static __device__ float d_qh[BH * NPOS * DHEAD];
static __device__ float d_kh[BH * NPOS * DHEAD];
static __device__ float d_vh[BH * NPOS * DHEAD];
static __device__ float d_ao[BATCH * NPOS * INNER];

#define YSTRIDE (BATCH * DIM * NPOS)

// ---------------- packed f32x2 helpers ----------------
typedef unsigned long long u64r;
__device__ __forceinline__ u64r pk2(float lo, float hi) {
    u64r r; asm("mov.b64 %0, {%1, %2};" : "=l"(r) : "f"(lo), "f"(hi)); return r;
}
__device__ __forceinline__ void upk2(u64r v, float& lo, float& hi) {
    asm("mov.b64 {%0, %1}, %2;" : "=f"(lo), "=f"(hi) : "l"(v));
}
__device__ __forceinline__ void ffma2(u64r& d, u64r a, u64r b) {
    asm("fma.rn.f32x2 %0, %1, %2, %0;" : "+l"(d) : "l"(a), "l"(b));
}
__device__ __forceinline__ u64r fmul2(u64r a, u64r b) {
    u64r r; asm("mul.rn.f32x2 %0, %1, %2;" : "=l"(r) : "l"(a), "l"(b)); return r;
}

__device__ __forceinline__ float mask_logit(float qm0, float qm1, float km0, float km1) {
    return __fmul_rn(__fadd_rn(__fmul_rn(qm0, km0), __fmul_rn(qm1, km1)), SCALE);
}

// strict total order: value desc, index asc (lax.top_k tie-break)
__device__ __forceinline__ bool topgt(float v1, int j1, float v2, int j2) {
    return v1 > v2 || (v1 == v2 && j1 < j2);
}
__device__ __forceinline__ void ce_keepmax(float& va, int& ia, float vb, int ib) {
    bool t = topgt(vb, ib, va, ia);
    va = t ? vb : va; ia = t ? ib : ia;
}
__device__ __forceinline__ void ce_sort(float& va, int& ia, float& vb, int& ib) {
    bool t = topgt(vb, ib, va, ia);
    float v = t ? vb : va; int i = t ? ib : ia;
    vb = t ? va : vb; ib = t ? ia : ib;
    va = v; ia = i;
}

// ---------------- kernel 0: transpose ----------------
__global__ void k_transpose(const float* __restrict__ x) {
    __shared__ float tile[32][33];
    int b = blockIdx.z;
    int p0 = blockIdx.x * 32, c0 = blockIdx.y * 32;
    int tx = threadIdx.x, ty = threadIdx.y;
    #pragma unroll
    for (int r = 0; r < 32; r += 8)
        tile[ty + r][tx] = x[(b * NPOS + p0 + ty + r) * DIM + c0 + tx];
    __syncthreads();
    #pragma unroll
    for (int r = 0; r < 32; r += 8)
        d_xt[(b * DIM + c0 + ty + r) * NPOS + p0 + tx] = tile[tx][ty + r];
}

// ---------------- kernel 1: channel mean/max ----------------
__global__ void k_meanmax(const float* __restrict__ x) {
    int bp = blockIdx.x;
    int b = bp >> 10, p = bp & 1023;
    int tid = threadIdx.x;
    float v = x[(b * NPOS + p) * DIM + tid];
    __shared__ float ss[256], sm[256];
    ss[tid] = v; sm[tid] = v;
    __syncthreads();
    for (int s = 128; s > 0; s >>= 1) {
        if (tid < s) { ss[tid] += ss[tid + s]; sm[tid] = fmaxf(sm[tid], sm[tid + s]); }
        __syncthreads();
    }
    if (tid == 0) {
        d_xattn[b * 2 * NPOS + p] = ss[0] * (1.f / 256.f);
        d_xattn[b * 2 * NPOS + NPOS + p] = sm[0];
    }
}

// ---------------- kernel 2: mask 3x3 convs ----------------
__global__ void k_maskconv(const float* __restrict__ qmw, const float* __restrict__ qmb,
                           const float* __restrict__ kmw, const float* __restrict__ kmb) {
    int idx = blockIdx.x * 256 + threadIdx.x;
    int b = idx >> 14;
    int rem = idx & 16383;
    int oc = rem >> 10;
    int p = rem & 1023;
    int py = p >> 5, px = p & 31;
    float aq = 0.f, ak = 0.f;
    #pragma unroll
    for (int ic = 0; ic < 2; ic++) {
        const float* xa = &d_xattn[(b * 2 + ic) * NPOS];
        #pragma unroll
        for (int ky = 0; ky < 3; ky++) {
            int iy = py + ky - 1;
            if ((unsigned)iy >= 32u) continue;
            #pragma unroll
            for (int kx = 0; kx < 3; kx++) {
                int ix = px + kx - 1;
                if ((unsigned)ix >= 32u) continue;
                float xv = xa[iy * 32 + ix];
                aq = fmaf(xv, qmw[((oc * 2 + ic) * 3 + ky) * 3 + kx], aq);
                ak = fmaf(xv, kmw[((oc * 2 + ic) * 3 + ky) * 3 + kx], ak);
            }
        }
    }
    aq += qmb[oc]; ak += kmb[oc];
    int h = oc >> 1, dd = oc & 1;
    d_qm[((b * HEADS + h) * NPOS + p) * 2 + dd] = aq;
    d_km[((b * HEADS + h) * NPOS + p) * 2 + dd] = ak;
}

// ---------------- kernel 3: warp-per-row mask stats + top-4 ----------------
__global__ void k_masktop() {
    int tid = threadIdx.x;
    int w = tid >> 5, lane = tid & 31;
    int row0 = blockIdx.x * 8;
    int bh = row0 >> 10;
    __shared__ float2 km2[NPOS];
    const float2* kmsrc = (const float2*)&d_km[bh * NPOS * 2];
    #pragma unroll
    for (int t = 0; t < 4; t++) km2[t * 256 + tid] = kmsrc[t * 256 + tid];
    __syncthreads();

    int row = row0 + w;
    float2 q2 = ((const float2*)d_qm)[row];

    float v0 = -CUDART_INF_F, v1 = -CUDART_INF_F, v2 = -CUDART_INF_F, v3 = -CUDART_INF_F;
    int j0i = 0x7fffffff, j1i = 0x7fffffff, j2i = 0x7fffffff, j3i = 0x7fffffff;

    // streaming insert: per-lane j strictly increases, so the (desc value, asc index)
    // test against stored entries reduces to plain l > v (ties keep older/lower index).
    #pragma unroll
    for (int t = 0; t < 32; t++) {
        int j = t * 32 + lane;
        float2 k2 = km2[j];
        float l = mask_logit(q2.x, q2.y, k2.x, k2.y);
        bool g0 = l > v0;
        bool g1 = l > v1;
        bool g2 = l > v2;
        bool g3 = l > v3;
        float nv3 = g3 ? (g2 ? v2 : l) : v3; int nj3 = g3 ? (g2 ? j2i : j) : j3i;
        float nv2 = g2 ? (g1 ? v1 : l) : v2; int nj2 = g2 ? (g1 ? j1i : j) : j2i;
        float nv1 = g1 ? (g0 ? v0 : l) : v1; int nj1 = g1 ? (g0 ? j0i : j) : j1i;
        float nv0 = g0 ? l : v0;             int nj0 = g0 ? j : j0i;
        v0 = nv0; v1 = nv1; v2 = nv2; v3 = nv3;
        j0i = nj0; j1i = nj1; j2i = nj2; j3i = nj3;
    }

    // cross-lane merge: full tie-break order (indices arbitrary across lanes)
    #pragma unroll
    for (int off = 16; off > 0; off >>= 1) {
        float o0 = __shfl_xor_sync(0xffffffffu, v0, off);
        float o1 = __shfl_xor_sync(0xffffffffu, v1, off);
        float o2 = __shfl_xor_sync(0xffffffffu, v2, off);
        float o3 = __shfl_xor_sync(0xffffffffu, v3, off);
        int p0 = __shfl_xor_sync(0xffffffffu, j0i, off);
        int p1 = __shfl_xor_sync(0xffffffffu, j1i, off);
        int p2 = __shfl_xor_sync(0xffffffffu, j2i, off);
        int p3 = __shfl_xor_sync(0xffffffffu, j3i, off);
        ce_keepmax(v0, j0i, o3, p3);
        ce_keepmax(v1, j1i, o2, p2);
        ce_keepmax(v2, j2i, o1, p1);
        ce_keepmax(v3, j3i, o0, p0);
        ce_sort(v0, j0i, v2, j2i);
        ce_sort(v1, j1i, v3, j3i);
        ce_sort(v0, j0i, v1, j1i);
        ce_sort(v2, j2i, v3, j3i);
    }

    float m = v0;
    float s = 0.f;
    #pragma unroll
    for (int t = 0; t < 32; t++) {
        int j = t * 32 + lane;
        float2 k2 = km2[j];
        float l = mask_logit(q2.x, q2.y, k2.x, k2.y);
        s += __expf(l - m);
    }
    #pragma unroll
    for (int off = 16; off > 0; off >>= 1) s += __shfl_xor_sync(0xffffffffu, s, off);

    if (lane == 0) {
        d_mmax[row] = m;
        d_msum[row] = s;
        d_top4[row * 4 + 0] = j0i;
        d_top4[row * 4 + 1] = j1i;
        d_top4[row * 4 + 2] = j2i;
        d_top4[row * 4 + 3] = j3i;
    }
}

// ---------------- depthwise 3x3 conv ----------------
__global__ void k_dwconv(const float* __restrict__ w0, const float* __restrict__ b0,
                         const float* __restrict__ w1, const float* __restrict__ b1,
                         const float* __restrict__ w2, const float* __restrict__ b2) {
    int c = blockIdx.x, b = blockIdx.y, br = blockIdx.z;
    const float* dw = (br == 0) ? w0 : (br == 1) ? w1 : w2;
    const float* db = (br == 0) ? b0 : (br == 1) ? b1 : b2;
    int tid = threadIdx.x;
    __shared__ float plane[NPOS];
    __shared__ float w[9];
    __shared__ float bias;
    const float* src = &d_xt[(b * DIM + c) * NPOS];
    #pragma unroll
    for (int t = 0; t < 4; t++) plane[t * 256 + tid] = src[t * 256 + tid];
    if (tid < 9) w[tid] = dw[c * 9 + tid];
    if (tid == 9) bias = db[c];
    __syncthreads();
    float* dst = &d_y[br * YSTRIDE + (b * DIM + c) * NPOS];
    #pragma unroll
    for (int t = 0; t < 4; t++) {
        int p = t * 256 + tid;
        int py = p >> 5, px = p & 31;
        float a = 0.f;
        #pragma unroll
        for (int ky = 0; ky < 3; ky++) {
            int iy = py + ky - 1;
            if ((unsigned)iy >= 32u) continue;
            #pragma unroll
            for (int kx = 0; kx < 3; kx++) {
                int ix = px + kx - 1;
                if ((unsigned)ix >= 32u) continue;
                a = fmaf(plane[iy * 32 + ix], w[ky * 3 + kx], a);
            }
        }
        dst[p] = a + bias;
    }
}

// ---------------- BN batch stats ----------------
__global__ void k_bnstats() {
    int c = blockIdx.x, br = blockIdx.y;
    int tid = threadIdx.x;
    float s = 0.f, ss = 0.f;
    for (int b = 0; b < BATCH; b++) {
        const float* src = &d_y[br * YSTRIDE + (b * DIM + c) * NPOS];
        #pragma unroll
        for (int t = 0; t < 4; t++) { float v = src[t * 256 + tid]; s += v; ss = fmaf(v, v, ss); }
    }
    __shared__ float r1[256], r2[256];
    r1[tid] = s; r2[tid] = ss;
    __syncthreads();
    for (int st = 128; st > 0; st >>= 1) {
        if (tid < st) { r1[tid] += r1[tid + st]; r2[tid] += r2[tid + st]; }
        __syncthreads();
    }
    if (tid == 0) {
        float mu = r1[0] * (1.f / 4096.f);
        float var = r2[0] * (1.f / 4096.f) - mu * mu;
        d_mean[br * DIM + c] = mu;
        d_var[br * DIM + c] = fmaxf(var, 0.f);
    }
}

// ---------------- BN normalize + exact GELU ----------------
__global__ void k_bngelu(const float* __restrict__ g0, const float* __restrict__ be0,
                         const float* __restrict__ g1, const float* __restrict__ be1,
                         const float* __restrict__ g2, const float* __restrict__ be2) {
    int br = blockIdx.y;
    const float* g = (br == 0) ? g0 : (br == 1) ? g1 : g2;
    const float* beta = (br == 0) ? be0 : (br == 1) ? be1 : be2;
    int idx = blockIdx.x * 256 + threadIdx.x;
    int c = (idx >> 10) & 255;
    float v = d_y[br * YSTRIDE + idx];
    float nv = (v - d_mean[br * DIM + c]) / sqrtf(d_var[br * DIM + c] + 1e-5f) * g[c] + beta[c];
    d_y[br * YSTRIDE + idx] = 0.5f * nv * (1.0f + erff(nv * 0.70710678118654752f));
}

// ---------------- pointwise 1x1 conv GEMM (FFMA2, dup-B in SMEM) ----------------
__global__ void k_pwgemm(const float* __restrict__ w0, const float* __restrict__ bb0,
                         const float* __restrict__ w1, const float* __restrict__ bb1,
                         const float* __restrict__ w2, const float* __restrict__ bb2) {
    __shared__ float As[32][68];
    __shared__ u64r Wsd[32][68];
    int br = blockIdx.z >> 2;
    int b = blockIdx.z & 3;
    const float* w = (br == 0) ? w0 : (br == 1) ? w1 : w2;
    const float* bias = (br == 0) ? bb0 : (br == 1) ? bb1 : bb2;
    float* out = (br == 0) ? d_qh : (br == 1) ? d_kh : d_vh;
    int oc0 = blockIdx.y * 64;
    int i0 = blockIdx.x * 64;
    int tid = threadIdx.x;
    int ty = tid >> 4, tx = tid & 15;
    u64r accp[4][2];
    #pragma unroll
    for (int r = 0; r < 4; r++) { accp[r][0] = 0ull; accp[r][1] = 0ull; }
    for (int c0 = 0; c0 < DIM; c0 += 32) {
        #pragma unroll
        for (int t = 0; t < 8; t++) {
            int idx = tid + t * 256;
            int ii = idx & 63, cc = idx >> 6;
            As[cc][ii] = d_y[br * YSTRIDE + (b * DIM + c0 + cc) * NPOS + i0 + ii];
        }
        #pragma unroll
        for (int t = 0; t < 8; t++) {
            int idx = tid + t * 256;
            int cc = idx & 31, o = idx >> 5;
            float wv = w[(oc0 + o) * DIM + c0 + cc];
            Wsd[cc][o] = pk2(wv, wv);
        }
        __syncthreads();
        #pragma unroll
        for (int cc = 0; cc < 32; cc++) {
            u64r a01 = *(const u64r*)&As[cc][tx * 4];
            u64r a23 = *(const u64r*)&As[cc][tx * 4 + 2];
            #pragma unroll
            for (int r = 0; r < 4; r++) {
                u64r ww = Wsd[cc][ty * 4 + r];
                ffma2(accp[r][0], a01, ww);
                ffma2(accp[r][1], a23, ww);
            }
        }
        __syncthreads();
    }
    #pragma unroll
    for (int r = 0; r < 4; r++) {
        int oc = oc0 + ty * 4 + r;
        int h = oc >> 6, dd = oc & 63;
        float bb = bias[oc];
        float c0v, c1v, c2v, c3v;
        upk2(accp[r][0], c0v, c1v);
        upk2(accp[r][1], c2v, c3v);
        float cv[4] = {c0v, c1v, c2v, c3v};
        #pragma unroll
        for (int cq = 0; cq < 4; cq++) {
            int ii = i0 + tx * 4 + cq;
            out[((b * HEADS + h) * NPOS + ii) * DHEAD + dd] = cv[cq] + bb;
        }
    }
}

// ---------------- fused attention (FFMA2, dup operands, dynamic smem) ----------------
#define QS_OFF   0
#define KSD_OFF  17408                     // 64*68*4
#define VS_OFF   (KSD_OFF + 64 * 35 * 8)   // +17920 = 35328
#define ESD_OFF  (VS_OFF + 32 * 68 * 4)    // +8704  = 44032
#define QM_OFF   (ESD_OFF + 32 * 67 * 8)   // +17152 = 61184
#define MMAX_OFF (QM_OFF + 512)
#define MINV_OFF (MMAX_OFF + 256)
#define TOP_OFF  (MINV_OFF + 256)
#define SMEM_ATTN (TOP_OFF + 1024)         // 63232 bytes

__global__ void k_attn() {
    extern __shared__ char smraw[];
    float (*Qs)[68]  = (float(*)[68])(smraw + QS_OFF);
    u64r  (*Ksd)[35] = (u64r(*)[35])(smraw + KSD_OFF);
    float (*Vs)[68]  = (float(*)[68])(smraw + VS_OFF);
    u64r  (*Esd)[67] = (u64r(*)[67])(smraw + ESD_OFF);
    float (*s_qm)[2] = (float(*)[2])(smraw + QM_OFF);
    float* s_mmax    = (float*)(smraw + MMAX_OFF);
    float* s_minv    = (float*)(smraw + MINV_OFF);
    int   (*s_top)[4] = (int(*)[4])(smraw + TOP_OFF);

    int i0 = blockIdx.x * 64;
    int bh = blockIdx.y;
    int tid = threadIdx.x;
    int ty = tid >> 4, tx = tid & 15;

    #pragma unroll
    for (int t = 0; t < 16; t++) {
        int idx = tid + t * 256;
        int dd = idx & 63, ii = idx >> 6;
        Qs[dd][ii] = d_qh[(bh * NPOS + i0 + ii) * DHEAD + dd];
    }
    if (tid < 64) {
        int ig = bh * NPOS + i0 + tid;
        s_qm[tid][0] = d_qm[ig * 2];
        s_qm[tid][1] = d_qm[ig * 2 + 1];
        s_mmax[tid] = d_mmax[ig];
        s_minv[tid] = 1.0f / d_msum[ig];
        #pragma unroll
        for (int t = 0; t < 4; t++) s_top[tid][t] = d_top4[ig * 4 + t];
    }
    __syncthreads();

    float run_max[4], run_sum[4];
    #pragma unroll
    for (int r = 0; r < 4; r++) { run_max[r] = -CUDART_INF_F; run_sum[r] = 0.f; }
    // PV accum: accp[r][cp] = row ty*4+r, col pair (tx*4+2cp, +1)
    u64r accp[4][2];
    #pragma unroll
    for (int r = 0; r < 4; r++) { accp[r][0] = 0ull; accp[r][1] = 0ull; }

    for (int j0 = 0; j0 < NPOS; j0 += 32) {
        #pragma unroll
        for (int t = 0; t < 8; t++) {
            int idx = tid + t * 256;
            int dd = idx & 63, jj = idx >> 6;
            float kv = d_kh[(bh * NPOS + j0 + jj) * DHEAD + dd];
            Ksd[dd][jj] = pk2(kv, kv);
            Vs[jj][dd] = d_vh[(bh * NPOS + j0 + jj) * DHEAD + dd];
        }
        __syncthreads();

        // QK: row-paired accumulators, dup-K broadcast
        u64r q00 = 0ull, q01 = 0ull, q10 = 0ull, q11 = 0ull;
        #pragma unroll
        for (int dd = 0; dd < 64; dd++) {
            u64r a01 = *(const u64r*)&Qs[dd][ty * 4];
            u64r a23 = *(const u64r*)&Qs[dd][ty * 4 + 2];
            u64r bb0 = Ksd[dd][tx * 2];
            u64r bb1 = Ksd[dd][tx * 2 + 1];
            ffma2(q00, a01, bb0);
            ffma2(q01, a01, bb1);
            ffma2(q10, a23, bb0);
            ffma2(q11, a23, bb1);
        }
        float sv[8];  // sv[r*2+cq]
        upk2(q00, sv[0], sv[2]);
        upk2(q01, sv[1], sv[3]);
        upk2(q10, sv[4], sv[6]);
        upk2(q11, sv[5], sv[7]);

        // mask epilogue
        #pragma unroll
        for (int cq = 0; cq < 2; cq++) {
            int jg = j0 + tx * 2 + cq;
            float2 k2 = ((const float2*)d_km)[bh * NPOS + jg];
            #pragma unroll
            for (int r = 0; r < 4; r++) {
                int il = ty * 4 + r;
                float ml = mask_logit(s_qm[il][0], s_qm[il][1], k2.x, k2.y);
                float dprob = __expf(ml - s_mmax[il]) * s_minv[il];
                float oneh = (jg == s_top[il][0] || jg == s_top[il][1] ||
                              jg == s_top[il][2] || jg == s_top[il][3]) ? 1.0f : -100000.0f;
                float maskv = __fadd_rn(__fadd_rn(oneh, -dprob), dprob);
                sv[r * 2 + cq] = __fmul_rn(__fmul_rn(sv[r * 2 + cq], SCALE), maskv);
            }
        }

        // tile row max across the 16-lane half-warp
        float tm[4];
        #pragma unroll
        for (int r = 0; r < 4; r++) tm[r] = fmaxf(sv[r * 2], sv[r * 2 + 1]);
        #pragma unroll
        for (int off = 1; off < 16; off <<= 1) {
            #pragma unroll
            for (int r = 0; r < 4; r++)
                tm[r] = fmaxf(tm[r], __shfl_xor_sync(0xffffffffu, tm[r], off));
        }

        // online softmax update + dup-Es write + acc rescale
        float fr[4];
        #pragma unroll
        for (int r = 0; r < 4; r++) {
            float nm = fmaxf(run_max[r], tm[r]);
            float f = __expf(run_max[r] - nm);   // 0 on first tile
            run_max[r] = nm;
            fr[r] = f;
            float e0 = __expf(sv[r * 2] - nm);
            float e1 = __expf(sv[r * 2 + 1] - nm);
            run_sum[r] = run_sum[r] * f + e0 + e1;
            Esd[tx * 2][ty * 4 + r]     = pk2(e0, e0);
            Esd[tx * 2 + 1][ty * 4 + r] = pk2(e1, e1);
        }
        #pragma unroll
        for (int r = 0; r < 4; r++) {
            u64r ffr = pk2(fr[r], fr[r]);
            accp[r][0] = fmul2(accp[r][0], ffr);
            accp[r][1] = fmul2(accp[r][1], ffr);
        }
        __syncthreads();

        // PV: col-paired accumulators, dup-E broadcast, natural V pairs
        #pragma unroll
        for (int jj = 0; jj < 32; jj++) {
            u64r b0 = *(const u64r*)&Vs[jj][tx * 4];
            u64r b1 = *(const u64r*)&Vs[jj][tx * 4 + 2];
            #pragma unroll
            for (int r = 0; r < 4; r++) {
                u64r a = Esd[jj][ty * 4 + r];
                ffma2(accp[r][0], a, b0);
                ffma2(accp[r][1], a, b1);
            }
        }
        __syncthreads();
    }

    #pragma unroll
    for (int off = 1; off < 16; off <<= 1) {
        #pragma unroll
        for (int r = 0; r < 4; r++)
            run_sum[r] += __shfl_xor_sync(0xffffffffu, run_sum[r], off);
    }

    int b = bh >> 3, h = bh & 7;
    #pragma unroll
    for (int r = 0; r < 4; r++) {
        int ii = i0 + ty * 4 + r;
        float inv = 1.0f / run_sum[r];
        float o0v, o1v, o2v, o3v;
        upk2(accp[r][0], o0v, o1v);
        upk2(accp[r][1], o2v, o3v);
        float4 st;
        st.x = o0v * inv; st.y = o1v * inv; st.z = o2v * inv; st.w = o3v * inv;
        *(float4*)&d_ao[((size_t)(b * NPOS + ii)) * INNER + h * DHEAD + tx * 4] = st;
    }
}

// ---------------- output GEMM (FFMA2, dup-W) ----------------
__global__ void k_out(const float* __restrict__ w, const float* __restrict__ ob, float* __restrict__ out) {
    __shared__ float As[32][68];
    __shared__ u64r Wsd[32][68];
    int o0 = blockIdx.x * 64;
    int bi0 = blockIdx.y * 64;
    int tid = threadIdx.x;
    int ty = tid >> 4, tx = tid & 15;
    u64r accp[4][2];
    #pragma unroll
    for (int r = 0; r < 4; r++) { accp[r][0] = 0ull; accp[r][1] = 0ull; }
    for (int c0 = 0; c0 < INNER; c0 += 32) {
        #pragma unroll
        for (int t = 0; t < 8; t++) {
            int idx = tid + t * 256;
            int cc = idx & 31, ii = idx >> 5;
            As[cc][ii] = d_ao[(size_t)(bi0 + ii) * INNER + c0 + cc];
        }
        #pragma unroll
        for (int t = 0; t < 8; t++) {
            int idx = tid + t * 256;
            int cc = idx & 31, o = idx >> 5;
            float wv = w[(o0 + o) * INNER + c0 + cc];
            Wsd[cc][o] = pk2(wv, wv);
        }
        __syncthreads();
        #pragma unroll
        for (int cc = 0; cc < 32; cc++) {
            u64r a01 = *(const u64r*)&As[cc][ty * 4];     // rows bi paired
            u64r a23 = *(const u64r*)&As[cc][ty * 4 + 2];
            #pragma unroll
            for (int r = 0; r < 4; r++) {
                u64r ww = Wsd[cc][tx * 4 + r];
                ffma2(accp[r][0], a01, ww);
                ffma2(accp[r][1], a23, ww);
            }
        }
        __syncthreads();
    }
    #pragma unroll
    for (int r = 0; r < 4; r++) {
        int o = o0 + tx * 4 + r;
        float b0v, b1v, b2v, b3v;
        upk2(accp[r][0], b0v, b1v);
        upk2(accp[r][1], b2v, b3v);
        float bv[4] = {b0v, b1v, b2v, b3v};
        float obv = ob[o];
        #pragma unroll
        for (int q = 0; q < 4; q++) {
            int bi = bi0 + ty * 4 + q;
            out[(size_t)bi * DIM + o] = bv[q] + obv;
        }
    }
}

// ---------------- launch ----------------
extern "C" void kernel_launch(void* const* d_in, const int* in_sizes, int n_in,
                              void* d_out, int out_size) {
    const float* x     = (const float*)d_in[0];
    const float* qd_w  = (const float*)d_in[1];
    const float* qd_b  = (const float*)d_in[2];
    const float* q_g   = (const float*)d_in[3];
    const float* q_be  = (const float*)d_in[4];
    const float* qp_w  = (const float*)d_in[5];
    const float* qp_b  = (const float*)d_in[6];
    const float* qm_w  = (const float*)d_in[7];
    const float* qm_b  = (const float*)d_in[8];
    const float* kd_w  = (const float*)d_in[9];
    const float* kd_b  = (const float*)d_in[10];
    const float* k_g   = (const float*)d_in[11];
    const float* k_be  = (const float*)d_in[12];
    const float* kp_w  = (const float*)d_in[13];
    const float* kp_b  = (const float*)d_in[14];
    const float* km_w  = (const float*)d_in[15];
    const float* km_b  = (const float*)d_in[16];
    const float* vd_w  = (const float*)d_in[17];
    const float* vd_b  = (const float*)d_in[18];
    const float* v_g   = (const float*)d_in[19];
    const float* v_be  = (const float*)d_in[20];
    const float* vp_w  = (const float*)d_in[21];
    const float* vp_b  = (const float*)d_in[22];
    const float* out_w = (const float*)d_in[25];
    const float* out_b = (const float*)d_in[26];
    float* out = (float*)d_out;

    // unconditional (idempotent, capture-legal; no static guards per harness rules)
    cudaFuncSetAttribute(k_attn, cudaFuncAttributeMaxDynamicSharedMemorySize, SMEM_ATTN);

    k_transpose<<<dim3(32, 8, 4), dim3(32, 8)>>>(x);
    k_meanmax<<<4096, 256>>>(x);
    k_maskconv<<<256, 256>>>(qm_w, qm_b, km_w, km_b);
    k_masktop<<<4096, 256>>>();

    k_dwconv<<<dim3(256, 4, 3), 256>>>(qd_w, qd_b, kd_w, kd_b, vd_w, vd_b);
    k_bnstats<<<dim3(256, 3), 256>>>();
    k_bngelu<<<dim3(4096, 3), 256>>>(q_g, q_be, k_g, k_be, v_g, v_be);
    k_pwgemm<<<dim3(16, 8, 12), 256>>>(qp_w, qp_b, kp_w, kp_b, vp_w, vp_b);

    k_attn<<<dim3(16, 32), 256, SMEM_ATTN>>>();
    k_out<<<dim3(4, 64), 256>>>(out_w, out_b, out);
}

// round 9
// speedup vs baseline: 1.4277x; 1.4277x over previous
#include <cuda_runtime.h>
#include <math.h>
#include <math_constants.h>

#define BATCH 4
#define DIM 256
#define IMG 32
#define NPOS 1024
#define HEADS 8
#define DHEAD 64
#define INNER 512
#define BH 32
#define SCALE 0.125f

// ---------------- scratch (device globals; no allocations) ----------------
static __device__ float d_xt[BATCH * DIM * NPOS];
static __device__ float d_xattn[BATCH * 2 * NPOS];
static __device__ float d_qm[BH * NPOS * 2];
static __device__ float d_km[BH * NPOS * 2];
static __device__ float d_mmax[BH * NPOS];
static __device__ float d_msum[BH * NPOS];
static __device__ int   d_top4[BH * NPOS * 4];
static __device__ float d_y[3 * BATCH * DIM * NPOS];
static __device__ float d_mean[3 * DIM];
static __device__ float d_var[3 * DIM];
static __device__ float d_qh[BH * NPOS * DHEAD];
static __device__ float d_kh[BH * NPOS * DHEAD];
static __device__ float d_vh[BH * NPOS * DHEAD];
static __device__ float d_ao[BATCH * NPOS * INNER];

#define YSTRIDE (BATCH * DIM * NPOS)

// ---------------- packed f32x2 helpers ----------------
typedef unsigned long long u64r;
__device__ __forceinline__ u64r pk2(float lo, float hi) {
    u64r r; asm("mov.b64 %0, {%1, %2};" : "=l"(r) : "f"(lo), "f"(hi)); return r;
}
__device__ __forceinline__ void upk2(u64r v, float& lo, float& hi) {
    asm("mov.b64 {%0, %1}, %2;" : "=f"(lo), "=f"(hi) : "l"(v));
}
__device__ __forceinline__ void ffma2(u64r& d, u64r a, u64r b) {
    asm("fma.rn.f32x2 %0, %1, %2, %0;" : "+l"(d) : "l"(a), "l"(b));
}
__device__ __forceinline__ u64r fmul2(u64r a, u64r b) {
    u64r r; asm("mul.rn.f32x2 %0, %1, %2;" : "=l"(r) : "l"(a), "l"(b)); return r;
}

__device__ __forceinline__ float mask_logit(float qm0, float qm1, float km0, float km1) {
    return __fmul_rn(__fadd_rn(__fmul_rn(qm0, km0), __fmul_rn(qm1, km1)), SCALE);
}

// strict total order: value desc, index asc (lax.top_k tie-break)
__device__ __forceinline__ bool topgt(float v1, int j1, float v2, int j2) {
    return v1 > v2 || (v1 == v2 && j1 < j2);
}
__device__ __forceinline__ void ce_keepmax(float& va, int& ia, float vb, int ib) {
    bool t = topgt(vb, ib, va, ia);
    va = t ? vb : va; ia = t ? ib : ia;
}
__device__ __forceinline__ void ce_sort(float& va, int& ia, float& vb, int& ib) {
    bool t = topgt(vb, ib, va, ia);
    float v = t ? vb : va; int i = t ? ib : ia;
    vb = t ? va : vb; ib = t ? ia : ib;
    va = v; ia = i;
}

// ---------------- kernel 0: transpose ----------------
__global__ void k_transpose(const float* __restrict__ x) {
    __shared__ float tile[32][33];
    int b = blockIdx.z;
    int p0 = blockIdx.x * 32, c0 = blockIdx.y * 32;
    int tx = threadIdx.x, ty = threadIdx.y;
    #pragma unroll
    for (int r = 0; r < 32; r += 8)
        tile[ty + r][tx] = x[(b * NPOS + p0 + ty + r) * DIM + c0 + tx];
    __syncthreads();
    #pragma unroll
    for (int r = 0; r < 32; r += 8)
        d_xt[(b * DIM + c0 + ty + r) * NPOS + p0 + tx] = tile[tx][ty + r];
}

// ---------------- kernel 1: channel mean/max ----------------
__global__ void k_meanmax(const float* __restrict__ x) {
    int bp = blockIdx.x;
    int b = bp >> 10, p = bp & 1023;
    int tid = threadIdx.x;
    float v = x[(b * NPOS + p) * DIM + tid];
    __shared__ float ss[256], sm[256];
    ss[tid] = v; sm[tid] = v;
    __syncthreads();
    for (int s = 128; s > 0; s >>= 1) {
        if (tid < s) { ss[tid] += ss[tid + s]; sm[tid] = fmaxf(sm[tid], sm[tid + s]); }
        __syncthreads();
    }
    if (tid == 0) {
        d_xattn[b * 2 * NPOS + p] = ss[0] * (1.f / 256.f);
        d_xattn[b * 2 * NPOS + NPOS + p] = sm[0];
    }
}

// ---------------- kernel 2: mask 3x3 convs ----------------
__global__ void k_maskconv(const float* __restrict__ qmw, const float* __restrict__ qmb,
                           const float* __restrict__ kmw, const float* __restrict__ kmb) {
    int idx = blockIdx.x * 256 + threadIdx.x;
    int b = idx >> 14;
    int rem = idx & 16383;
    int oc = rem >> 10;
    int p = rem & 1023;
    int py = p >> 5, px = p & 31;
    float aq = 0.f, ak = 0.f;
    #pragma unroll
    for (int ic = 0; ic < 2; ic++) {
        const float* xa = &d_xattn[(b * 2 + ic) * NPOS];
        #pragma unroll
        for (int ky = 0; ky < 3; ky++) {
            int iy = py + ky - 1;
            if ((unsigned)iy >= 32u) continue;
            #pragma unroll
            for (int kx = 0; kx < 3; kx++) {
                int ix = px + kx - 1;
                if ((unsigned)ix >= 32u) continue;
                float xv = xa[iy * 32 + ix];
                aq = fmaf(xv, qmw[((oc * 2 + ic) * 3 + ky) * 3 + kx], aq);
                ak = fmaf(xv, kmw[((oc * 2 + ic) * 3 + ky) * 3 + kx], ak);
            }
        }
    }
    aq += qmb[oc]; ak += kmb[oc];
    int h = oc >> 1, dd = oc & 1;
    d_qm[((b * HEADS + h) * NPOS + p) * 2 + dd] = aq;
    d_km[((b * HEADS + h) * NPOS + p) * 2 + dd] = ak;
}

// ---------------- kernel 3: warp-per-row mask stats + top-4 ----------------
__global__ void k_masktop() {
    int tid = threadIdx.x;
    int w = tid >> 5, lane = tid & 31;
    int row0 = blockIdx.x * 8;
    int bh = row0 >> 10;
    __shared__ float2 km2[NPOS];
    const float2* kmsrc = (const float2*)&d_km[bh * NPOS * 2];
    #pragma unroll
    for (int t = 0; t < 4; t++) km2[t * 256 + tid] = kmsrc[t * 256 + tid];
    __syncthreads();

    int row = row0 + w;
    float2 q2 = ((const float2*)d_qm)[row];

    float v0 = -CUDART_INF_F, v1 = -CUDART_INF_F, v2 = -CUDART_INF_F, v3 = -CUDART_INF_F;
    int j0i = 0x7fffffff, j1i = 0x7fffffff, j2i = 0x7fffffff, j3i = 0x7fffffff;

    // streaming insert: per-lane j strictly increases, so the (desc value, asc index)
    // test against stored entries reduces to plain l > v (ties keep older/lower index).
    #pragma unroll
    for (int t = 0; t < 32; t++) {
        int j = t * 32 + lane;
        float2 k2 = km2[j];
        float l = mask_logit(q2.x, q2.y, k2.x, k2.y);
        bool g0 = l > v0;
        bool g1 = l > v1;
        bool g2 = l > v2;
        bool g3 = l > v3;
        float nv3 = g3 ? (g2 ? v2 : l) : v3; int nj3 = g3 ? (g2 ? j2i : j) : j3i;
        float nv2 = g2 ? (g1 ? v1 : l) : v2; int nj2 = g2 ? (g1 ? j1i : j) : j2i;
        float nv1 = g1 ? (g0 ? v0 : l) : v1; int nj1 = g1 ? (g0 ? j0i : j) : j1i;
        float nv0 = g0 ? l : v0;             int nj0 = g0 ? j : j0i;
        v0 = nv0; v1 = nv1; v2 = nv2; v3 = nv3;
        j0i = nj0; j1i = nj1; j2i = nj2; j3i = nj3;
    }

    // cross-lane merge: full tie-break order (indices arbitrary across lanes)
    #pragma unroll
    for (int off = 16; off > 0; off >>= 1) {
        float o0 = __shfl_xor_sync(0xffffffffu, v0, off);
        float o1 = __shfl_xor_sync(0xffffffffu, v1, off);
        float o2 = __shfl_xor_sync(0xffffffffu, v2, off);
        float o3 = __shfl_xor_sync(0xffffffffu, v3, off);
        int p0 = __shfl_xor_sync(0xffffffffu, j0i, off);
        int p1 = __shfl_xor_sync(0xffffffffu, j1i, off);
        int p2 = __shfl_xor_sync(0xffffffffu, j2i, off);
        int p3 = __shfl_xor_sync(0xffffffffu, j3i, off);
        ce_keepmax(v0, j0i, o3, p3);
        ce_keepmax(v1, j1i, o2, p2);
        ce_keepmax(v2, j2i, o1, p1);
        ce_keepmax(v3, j3i, o0, p0);
        ce_sort(v0, j0i, v2, j2i);
        ce_sort(v1, j1i, v3, j3i);
        ce_sort(v0, j0i, v1, j1i);
        ce_sort(v2, j2i, v3, j3i);
    }

    float m = v0;
    float s = 0.f;
    #pragma unroll
    for (int t = 0; t < 32; t++) {
        int j = t * 32 + lane;
        float2 k2 = km2[j];
        float l = mask_logit(q2.x, q2.y, k2.x, k2.y);
        s += __expf(l - m);
    }
    #pragma unroll
    for (int off = 16; off > 0; off >>= 1) s += __shfl_xor_sync(0xffffffffu, s, off);

    if (lane == 0) {
        d_mmax[row] = m;
        d_msum[row] = s;
        d_top4[row * 4 + 0] = j0i;
        d_top4[row * 4 + 1] = j1i;
        d_top4[row * 4 + 2] = j2i;
        d_top4[row * 4 + 3] = j3i;
    }
}

// ---------------- depthwise 3x3 conv ----------------
__global__ void k_dwconv(const float* __restrict__ w0, const float* __restrict__ b0,
                         const float* __restrict__ w1, const float* __restrict__ b1,
                         const float* __restrict__ w2, const float* __restrict__ b2) {
    int c = blockIdx.x, b = blockIdx.y, br = blockIdx.z;
    const float* dw = (br == 0) ? w0 : (br == 1) ? w1 : w2;
    const float* db = (br == 0) ? b0 : (br == 1) ? b1 : b2;
    int tid = threadIdx.x;
    __shared__ float plane[NPOS];
    __shared__ float w[9];
    __shared__ float bias;
    const float* src = &d_xt[(b * DIM + c) * NPOS];
    #pragma unroll
    for (int t = 0; t < 4; t++) plane[t * 256 + tid] = src[t * 256 + tid];
    if (tid < 9) w[tid] = dw[c * 9 + tid];
    if (tid == 9) bias = db[c];
    __syncthreads();
    float* dst = &d_y[br * YSTRIDE + (b * DIM + c) * NPOS];
    #pragma unroll
    for (int t = 0; t < 4; t++) {
        int p = t * 256 + tid;
        int py = p >> 5, px = p & 31;
        float a = 0.f;
        #pragma unroll
        for (int ky = 0; ky < 3; ky++) {
            int iy = py + ky - 1;
            if ((unsigned)iy >= 32u) continue;
            #pragma unroll
            for (int kx = 0; kx < 3; kx++) {
                int ix = px + kx - 1;
                if ((unsigned)ix >= 32u) continue;
                a = fmaf(plane[iy * 32 + ix], w[ky * 3 + kx], a);
            }
        }
        dst[p] = a + bias;
    }
}

// ---------------- BN batch stats ----------------
__global__ void k_bnstats() {
    int c = blockIdx.x, br = blockIdx.y;
    int tid = threadIdx.x;
    float s = 0.f, ss = 0.f;
    for (int b = 0; b < BATCH; b++) {
        const float* src = &d_y[br * YSTRIDE + (b * DIM + c) * NPOS];
        #pragma unroll
        for (int t = 0; t < 4; t++) { float v = src[t * 256 + tid]; s += v; ss = fmaf(v, v, ss); }
    }
    __shared__ float r1[256], r2[256];
    r1[tid] = s; r2[tid] = ss;
    __syncthreads();
    for (int st = 128; st > 0; st >>= 1) {
        if (tid < st) { r1[tid] += r1[tid + st]; r2[tid] += r2[tid + st]; }
        __syncthreads();
    }
    if (tid == 0) {
        float mu = r1[0] * (1.f / 4096.f);
        float var = r2[0] * (1.f / 4096.f) - mu * mu;
        d_mean[br * DIM + c] = mu;
        d_var[br * DIM + c] = fmaxf(var, 0.f);
    }
}

// ---------------- BN normalize + exact GELU ----------------
__global__ void k_bngelu(const float* __restrict__ g0, const float* __restrict__ be0,
                         const float* __restrict__ g1, const float* __restrict__ be1,
                         const float* __restrict__ g2, const float* __restrict__ be2) {
    int br = blockIdx.y;
    const float* g = (br == 0) ? g0 : (br == 1) ? g1 : g2;
    const float* beta = (br == 0) ? be0 : (br == 1) ? be1 : be2;
    int idx = blockIdx.x * 256 + threadIdx.x;
    int c = (idx >> 10) & 255;
    float v = d_y[br * YSTRIDE + idx];
    float nv = (v - d_mean[br * DIM + c]) / sqrtf(d_var[br * DIM + c] + 1e-5f) * g[c] + beta[c];
    d_y[br * YSTRIDE + idx] = 0.5f * nv * (1.0f + erff(nv * 0.70710678118654752f));
}

// ---------------- pointwise 1x1 conv GEMM (FFMA2) ----------------
__global__ void k_pwgemm(const float* __restrict__ w0, const float* __restrict__ bb0,
                         const float* __restrict__ w1, const float* __restrict__ bb1,
                         const float* __restrict__ w2, const float* __restrict__ bb2) {
    __shared__ float As[32][68];
    __shared__ float Ws[32][68];
    int br = blockIdx.z >> 2;
    int b = blockIdx.z & 3;
    const float* w = (br == 0) ? w0 : (br == 1) ? w1 : w2;
    const float* bias = (br == 0) ? bb0 : (br == 1) ? bb1 : bb2;
    float* out = (br == 0) ? d_qh : (br == 1) ? d_kh : d_vh;
    int oc0 = blockIdx.y * 64;
    int i0 = blockIdx.x * 64;
    int tid = threadIdx.x;
    int ty = tid >> 4, tx = tid & 15;
    u64r accp[4][2];
    #pragma unroll
    for (int r = 0; r < 4; r++) { accp[r][0] = 0ull; accp[r][1] = 0ull; }
    for (int c0 = 0; c0 < DIM; c0 += 32) {
        #pragma unroll
        for (int t = 0; t < 8; t++) {
            int idx = tid + t * 256;
            int ii = idx & 63, cc = idx >> 6;
            As[cc][ii] = d_y[br * YSTRIDE + (b * DIM + c0 + cc) * NPOS + i0 + ii];
        }
        #pragma unroll
        for (int t = 0; t < 8; t++) {
            int idx = tid + t * 256;
            int cc = idx & 31, o = idx >> 5;
            Ws[cc][o] = w[(oc0 + o) * DIM + c0 + cc];
        }
        __syncthreads();
        #pragma unroll
        for (int cc = 0; cc < 32; cc++) {
            u64r a01 = *(const u64r*)&As[cc][tx * 4];
            u64r a23 = *(const u64r*)&As[cc][tx * 4 + 2];
            #pragma unroll
            for (int r = 0; r < 4; r++) {
                float wv = Ws[cc][ty * 4 + r];
                u64r ww = pk2(wv, wv);
                ffma2(accp[r][0], a01, ww);
                ffma2(accp[r][1], a23, ww);
            }
        }
        __syncthreads();
    }
    #pragma unroll
    for (int r = 0; r < 4; r++) {
        int oc = oc0 + ty * 4 + r;
        int h = oc >> 6, dd = oc & 63;
        float bb = bias[oc];
        float c0v, c1v, c2v, c3v;
        upk2(accp[r][0], c0v, c1v);
        upk2(accp[r][1], c2v, c3v);
        float cv[4] = {c0v, c1v, c2v, c3v};
        #pragma unroll
        for (int cq = 0; cq < 4; cq++) {
            int ii = i0 + tx * 4 + cq;
            out[((b * HEADS + h) * NPOS + ii) * DHEAD + dd] = cv[cq] + bb;
        }
    }
}

// ---------------- fused attention (FFMA2): QK*mask -> online softmax -> PV ----------------
__global__ void k_attn() {
    __shared__ float Qs[64][68];    // [dd][ii]
    __shared__ float Ks[64][33];    // [dd][jj]
    __shared__ float Vs[32][68];    // [jj][dd]
    __shared__ float Es[32][68];    // [jj][ii]
    __shared__ float s_qm[64][2];
    __shared__ float s_mmax[64];
    __shared__ float s_minv[64];
    __shared__ int   s_top[64][4];

    int i0 = blockIdx.x * 64;
    int bh = blockIdx.y;
    int tid = threadIdx.x;
    int ty = tid >> 4, tx = tid & 15;

    #pragma unroll
    for (int t = 0; t < 16; t++) {
        int idx = tid + t * 256;
        int dd = idx & 63, ii = idx >> 6;
        Qs[dd][ii] = d_qh[(bh * NPOS + i0 + ii) * DHEAD + dd];
    }
    if (tid < 64) {
        int ig = bh * NPOS + i0 + tid;
        s_qm[tid][0] = d_qm[ig * 2];
        s_qm[tid][1] = d_qm[ig * 2 + 1];
        s_mmax[tid] = d_mmax[ig];
        s_minv[tid] = 1.0f / d_msum[ig];
        #pragma unroll
        for (int t = 0; t < 4; t++) s_top[tid][t] = d_top4[ig * 4 + t];
    }
    __syncthreads();

    float run_max[4], run_sum[4];
    #pragma unroll
    for (int r = 0; r < 4; r++) { run_max[r] = -CUDART_INF_F; run_sum[r] = 0.f; }
    // PV accum, row-paired: accp[rp][c] = rows (ty*4+2rp, +1), col d = tx*4+c
    u64r accp[2][4];
    #pragma unroll
    for (int c = 0; c < 4; c++) { accp[0][c] = 0ull; accp[1][c] = 0ull; }

    for (int j0 = 0; j0 < NPOS; j0 += 32) {
        #pragma unroll
        for (int t = 0; t < 8; t++) {
            int idx = tid + t * 256;
            int dd = idx & 63, jj = idx >> 6;
            Ks[dd][jj] = d_kh[(bh * NPOS + j0 + jj) * DHEAD + dd];
            Vs[jj][dd] = d_vh[(bh * NPOS + j0 + jj) * DHEAD + dd];
        }
        __syncthreads();

        // QK sub-tile, row-paired: q[rp][cq] = rows (2rp,2rp+1) x j = tx*2+cq
        u64r q00 = 0ull, q01 = 0ull, q10 = 0ull, q11 = 0ull;
        #pragma unroll
        for (int dd = 0; dd < 64; dd++) {
            u64r a01 = *(const u64r*)&Qs[dd][ty * 4];
            u64r a23 = *(const u64r*)&Qs[dd][ty * 4 + 2];
            float b0 = Ks[dd][tx * 2];
            float b1 = Ks[dd][tx * 2 + 1];
            u64r bb0 = pk2(b0, b0);
            u64r bb1 = pk2(b1, b1);
            ffma2(q00, a01, bb0);
            ffma2(q01, a01, bb1);
            ffma2(q10, a23, bb0);
            ffma2(q11, a23, bb1);
        }
        float sv[8];  // sv[r*2+cq]
        upk2(q00, sv[0], sv[2]);
        upk2(q01, sv[1], sv[3]);
        upk2(q10, sv[4], sv[6]);
        upk2(q11, sv[5], sv[7]);

        // mask epilogue
        #pragma unroll
        for (int cq = 0; cq < 2; cq++) {
            int jg = j0 + tx * 2 + cq;
            float2 k2 = ((const float2*)d_km)[bh * NPOS + jg];
            #pragma unroll
            for (int r = 0; r < 4; r++) {
                int il = ty * 4 + r;
                float ml = mask_logit(s_qm[il][0], s_qm[il][1], k2.x, k2.y);
                float dprob = __expf(ml - s_mmax[il]) * s_minv[il];
                float oneh = (jg == s_top[il][0] || jg == s_top[il][1] ||
                              jg == s_top[il][2] || jg == s_top[il][3]) ? 1.0f : -100000.0f;
                float maskv = __fadd_rn(__fadd_rn(oneh, -dprob), dprob);
                sv[r * 2 + cq] = __fmul_rn(__fmul_rn(sv[r * 2 + cq], SCALE), maskv);
            }
        }

        // tile row max across the 16-lane half-warp
        float tm[4];
        #pragma unroll
        for (int r = 0; r < 4; r++) tm[r] = fmaxf(sv[r * 2], sv[r * 2 + 1]);
        #pragma unroll
        for (int off = 1; off < 16; off <<= 1) {
            #pragma unroll
            for (int r = 0; r < 4; r++)
                tm[r] = fmaxf(tm[r], __shfl_xor_sync(0xffffffffu, tm[r], off));
        }

        // online softmax update + Es write + acc rescale
        float fr[4];
        #pragma unroll
        for (int r = 0; r < 4; r++) {
            float nm = fmaxf(run_max[r], tm[r]);
            float f = __expf(run_max[r] - nm);   // 0 on first tile
            run_max[r] = nm;
            fr[r] = f;
            float e0 = __expf(sv[r * 2] - nm);
            float e1 = __expf(sv[r * 2 + 1] - nm);
            run_sum[r] = run_sum[r] * f + e0 + e1;
            Es[tx * 2][ty * 4 + r]     = e0;
            Es[tx * 2 + 1][ty * 4 + r] = e1;
        }
        {
            u64r ff0 = pk2(fr[0], fr[1]);
            u64r ff1 = pk2(fr[2], fr[3]);
            #pragma unroll
            for (int c = 0; c < 4; c++) {
                accp[0][c] = fmul2(accp[0][c], ff0);
                accp[1][c] = fmul2(accp[1][c], ff1);
            }
        }
        __syncthreads();

        // PV accumulate (row-paired)
        #pragma unroll
        for (int jj = 0; jj < 32; jj++) {
            u64r a01 = *(const u64r*)&Es[jj][ty * 4];
            u64r a23 = *(const u64r*)&Es[jj][ty * 4 + 2];
            #pragma unroll
            for (int c = 0; c < 4; c++) {
                float bvv = Vs[jj][tx * 4 + c];
                u64r bb = pk2(bvv, bvv);
                ffma2(accp[0][c], a01, bb);
                ffma2(accp[1][c], a23, bb);
            }
        }
        __syncthreads();
    }

    #pragma unroll
    for (int off = 1; off < 16; off <<= 1) {
        #pragma unroll
        for (int r = 0; r < 4; r++)
            run_sum[r] += __shfl_xor_sync(0xffffffffu, run_sum[r], off);
    }
    // unpack: rows r = 2rp + hi
    float ov[4][4];
    #pragma unroll
    for (int rp = 0; rp < 2; rp++)
        #pragma unroll
        for (int c = 0; c < 4; c++)
            upk2(accp[rp][c], ov[2 * rp][c], ov[2 * rp + 1][c]);

    int b = bh >> 3, h = bh & 7;
    #pragma unroll
    for (int r = 0; r < 4; r++) {
        int ii = i0 + ty * 4 + r;
        float inv = 1.0f / run_sum[r];
        float4 st;
        #pragma unroll
        for (int c = 0; c < 4; c++) ((float*)&st)[c] = ov[r][c] * inv;
        *(float4*)&d_ao[((size_t)(b * NPOS + ii)) * INNER + h * DHEAD + tx * 4] = st;
    }
}

// ---------------- output GEMM (FFMA2) ----------------
__global__ void k_out(const float* __restrict__ w, const float* __restrict__ ob, float* __restrict__ out) {
    __shared__ float As[32][68];
    __shared__ float Ws[32][68];
    int o0 = blockIdx.x * 64;
    int bi0 = blockIdx.y * 64;
    int tid = threadIdx.x;
    int ty = tid >> 4, tx = tid & 15;
    u64r accp[4][2];
    #pragma unroll
    for (int r = 0; r < 4; r++) { accp[r][0] = 0ull; accp[r][1] = 0ull; }
    for (int c0 = 0; c0 < INNER; c0 += 32) {
        #pragma unroll
        for (int t = 0; t < 8; t++) {
            int idx = tid + t * 256;
            int cc = idx & 31, ii = idx >> 5;
            As[cc][ii] = d_ao[(size_t)(bi0 + ii) * INNER + c0 + cc];
        }
        #pragma unroll
        for (int t = 0; t < 8; t++) {
            int idx = tid + t * 256;
            int cc = idx & 31, o = idx >> 5;
            Ws[cc][o] = w[(o0 + o) * INNER + c0 + cc];
        }
        __syncthreads();
        #pragma unroll
        for (int cc = 0; cc < 32; cc++) {
            u64r a01 = *(const u64r*)&As[cc][ty * 4];     // rows bi paired
            u64r a23 = *(const u64r*)&As[cc][ty * 4 + 2];
            #pragma unroll
            for (int r = 0; r < 4; r++) {
                float wv = Ws[cc][tx * 4 + r];
                u64r ww = pk2(wv, wv);
                ffma2(accp[r][0], a01, ww);
                ffma2(accp[r][1], a23, ww);
            }
        }
        __syncthreads();
    }
    // accp[r][p]: output cols o = o0+tx*4+r, rows bi = bi0+ty*4+(2p+hi)
    #pragma unroll
    for (int r = 0; r < 4; r++) {
        int o = o0 + tx * 4 + r;
        float b0v, b1v, b2v, b3v;
        upk2(accp[r][0], b0v, b1v);
        upk2(accp[r][1], b2v, b3v);
        float bv[4] = {b0v, b1v, b2v, b3v};
        float obv = ob[o];
        #pragma unroll
        for (int q = 0; q < 4; q++) {
            int bi = bi0 + ty * 4 + q;
            out[(size_t)bi * DIM + o] = bv[q] + obv;
        }
    }
}

// ---------------- launch ----------------
extern "C" void kernel_launch(void* const* d_in, const int* in_sizes, int n_in,
                              void* d_out, int out_size) {
    const float* x     = (const float*)d_in[0];
    const float* qd_w  = (const float*)d_in[1];
    const float* qd_b  = (const float*)d_in[2];
    const float* q_g   = (const float*)d_in[3];
    const float* q_be  = (const float*)d_in[4];
    const float* qp_w  = (const float*)d_in[5];
    const float* qp_b  = (const float*)d_in[6];
    const float* qm_w  = (const float*)d_in[7];
    const float* qm_b  = (const float*)d_in[8];
    const float* kd_w  = (const float*)d_in[9];
    const float* kd_b  = (const float*)d_in[10];
    const float* k_g   = (const float*)d_in[11];
    const float* k_be  = (const float*)d_in[12];
    const float* kp_w  = (const float*)d_in[13];
    const float* kp_b  = (const float*)d_in[14];
    const float* km_w  = (const float*)d_in[15];
    const float* km_b  = (const float*)d_in[16];
    const float* vd_w  = (const float*)d_in[17];
    const float* vd_b  = (const float*)d_in[18];
    const float* v_g   = (const float*)d_in[19];
    const float* v_be  = (const float*)d_in[20];
    const float* vp_w  = (const float*)d_in[21];
    const float* vp_b  = (const float*)d_in[22];
    const float* out_w = (const float*)d_in[25];
    const float* out_b = (const float*)d_in[26];
    float* out = (float*)d_out;

    k_transpose<<<dim3(32, 8, 4), dim3(32, 8)>>>(x);
    k_meanmax<<<4096, 256>>>(x);
    k_maskconv<<<256, 256>>>(qm_w, qm_b, km_w, km_b);
    k_masktop<<<4096, 256>>>();

    k_dwconv<<<dim3(256, 4, 3), 256>>>(qd_w, qd_b, kd_w, kd_b, vd_w, vd_b);
    k_bnstats<<<dim3(256, 3), 256>>>();
    k_bngelu<<<dim3(4096, 3), 256>>>(q_g, q_be, k_g, k_be, v_g, v_be);
    k_pwgemm<<<dim3(16, 8, 12), 256>>>(qp_w, qp_b, kp_w, kp_b, vp_w, vp_b);

    k_attn<<<dim3(16, 32), 256>>>();
    k_out<<<dim3(4, 64), 256>>>(out_w, out_b, out);
}